// round 14
// baseline (speedup 1.0000x reference)
#include <cuda_runtime.h>
#include <cuda_bf16.h>
#include <cstdint>

// Problem constants
#define BB 2
#define NN 8192
#define CC 128
#define PP 3
#define KK 16
#define NPTS (BB*NN)          // 16384 total points
#define EPS 1e-5f

#define WS2 136               // bf16 row stride for MMA operands (conflict-free)

// ---------------- scratch (static device globals; no allocation) ----------------
__device__ __nv_bfloat16 d_w1h[128*WS2];  // W1x hi-split [o][c]
__device__ __nv_bfloat16 d_w1l[128*WS2];
__device__ float         d_w1p[128*3];    // W1 pos part (exact fp32)
__device__ __nv_bfloat16 d_w2h[128*WS2];
__device__ __nv_bfloat16 d_w2l[128*WS2];
__device__ __nv_bfloat16 d_m1h[128*WS2];
__device__ __nv_bfloat16 d_m1l[128*WS2];
__device__ __nv_bfloat16 d_m2h[128*WS2];
__device__ __nv_bfloat16 d_m2l[128*WS2];
__device__ int   d_nbr[NPTS*KK];
__device__ float d_u [NPTS*CC];
__device__ float d_wself[NPTS*CC];
__device__ float d_res[NPTS*CC];
__device__ float d_t [NPTS*CC];
__device__ float d_p1[128*128];
__device__ float d_p2[128*128];
__device__ float d_scale1[CC], d_shift1[CC], d_scale2[CC], d_shift2[CC];

// ---------------- mma/ldmatrix helpers (baseline PTX) ----------------
__device__ __forceinline__ void mma16816(float* c, const uint32_t* a, const uint32_t* b) {
    asm volatile(
        "mma.sync.aligned.m16n8k16.row.col.f32.bf16.bf16.f32 "
        "{%0,%1,%2,%3}, {%4,%5,%6,%7}, {%8,%9}, {%0,%1,%2,%3};"
        : "+f"(c[0]), "+f"(c[1]), "+f"(c[2]), "+f"(c[3])
        : "r"(a[0]), "r"(a[1]), "r"(a[2]), "r"(a[3]), "r"(b[0]), "r"(b[1]));
}
__device__ __forceinline__ void ldsm_x4(uint32_t addr, uint32_t* r) {
    asm volatile("ldmatrix.sync.aligned.m8n8.x4.shared.b16 {%0,%1,%2,%3}, [%4];"
        : "=r"(r[0]), "=r"(r[1]), "=r"(r[2]), "=r"(r[3]) : "r"(addr));
}
__device__ __forceinline__ uint32_t smem_u32(const void* p) {
    return (uint32_t)__cvta_generic_to_shared(p);
}
__device__ __forceinline__ void split_store(__nv_bfloat16* H, __nv_bfloat16* L,
                                            int off, float a, float b) {
    __nv_bfloat162 hi = __floats2bfloat162_rn(a, b);
    __nv_bfloat162 lo = __floats2bfloat162_rn(a - __low2float(hi), b - __high2float(hi));
    *(__nv_bfloat162*)&H[off] = hi;
    *(__nv_bfloat162*)&L[off] = lo;
}

// ldmatrix lane offsets (bytes) — reproduce the scalar fragment layout exactly.
#define AOFF(lane) ((uint32_t)((((lane)&7) + (((lane)>>3)&1)*8)*WS2*2 + ((lane)>>4)*16))
#define BOFF(lane) ((uint32_t)((((lane)&7) + ((lane)>>4)*8)*WS2*2 + (((lane)>>3)&1)*16))

// GEMM term, 32x32 warp tile (4 nt), acc[2][4][4]
#define GEMM_TERM44(Au, Bu, ACC_) \
    { \
        const uint32_t ab = (Au) + (uint32_t)(m0*WS2*2) + aoff; \
        const uint32_t bb = (Bu) + (uint32_t)(n0*WS2*2) + boff; \
        _Pragma("unroll") \
        for (int kk = 0; kk < 128; kk += 16) { \
            uint32_t a[2][4], bfr[2][4]; \
            ldsm_x4(ab + (kk<<1), a[0]); \
            ldsm_x4(ab + 16*WS2*2 + (kk<<1), a[1]); \
            _Pragma("unroll") \
            for (int j = 0; j < 2; j++) ldsm_x4(bb + j*16*WS2*2 + (kk<<1), bfr[j]); \
            _Pragma("unroll") \
            for (int mt = 0; mt < 2; mt++) \
                _Pragma("unroll") \
                for (int j = 0; j < 2; j++) { \
                    mma16816(ACC_[mt][2*j],   a[mt], &bfr[j][0]); \
                    mma16816(ACC_[mt][2*j+1], a[mt], &bfr[j][2]); \
                } \
        } \
    }

// GEMM term, 32x64 warp tile (8 nt), acc[2][8][4]
#define GEMM_TERM48(Au, Bu) \
    { \
        const uint32_t ab = (Au) + (uint32_t)(m0*WS2*2) + aoff; \
        const uint32_t bb = (Bu) + (uint32_t)(n0*WS2*2) + boff; \
        _Pragma("unroll") \
        for (int kk = 0; kk < 128; kk += 16) { \
            uint32_t a[2][4], bfr[4][4]; \
            ldsm_x4(ab + (kk<<1), a[0]); \
            ldsm_x4(ab + 16*WS2*2 + (kk<<1), a[1]); \
            _Pragma("unroll") \
            for (int j = 0; j < 4; j++) ldsm_x4(bb + j*16*WS2*2 + (kk<<1), bfr[j]); \
            _Pragma("unroll") \
            for (int mt = 0; mt < 2; mt++) \
                _Pragma("unroll") \
                for (int j = 0; j < 4; j++) { \
                    mma16816(acc[mt][2*j],   a[mt], &bfr[j][0]); \
                    mma16816(acc[mt][2*j+1], a[mt], &bfr[j][2]); \
                } \
        } \
    }

// ---------------- prep: build all bf16 weight splits ----------------
__global__ void prep_kernel(const float* __restrict__ w1, const float* __restrict__ w2,
                            const float* __restrict__ m1, const float* __restrict__ m2) {
    int i = blockIdx.x*blockDim.x + threadIdx.x;
    if (i < 128*128) {
        int o = i>>7, c = i&127;
        int off = o*WS2 + c;
        {
            float w = w1[o*131 + c];
            __nv_bfloat16 hi = __float2bfloat16(w);
            d_w1h[off] = hi; d_w1l[off] = __float2bfloat16(w - __bfloat162float(hi));
        }
        {
            float w = w2[i];
            __nv_bfloat16 hi = __float2bfloat16(w);
            d_w2h[off] = hi; d_w2l[off] = __float2bfloat16(w - __bfloat162float(hi));
        }
        {
            float w = m1[i];
            __nv_bfloat16 hi = __float2bfloat16(w);
            d_m1h[off] = hi; d_m1l[off] = __float2bfloat16(w - __bfloat162float(hi));
        }
        {
            float w = m2[i];
            __nv_bfloat16 hi = __float2bfloat16(w);
            d_m2h[off] = hi; d_m2l[off] = __float2bfloat16(w - __bfloat162float(hi));
        }
        if (c < 3) d_w1p[o*3 + c] = w1[o*131 + 128 + c];
    }
}

// ---------------- KNN: single pass, sortable-u64 (dist,idx) keys ----------------
// key = (order-preserving uint of d) << 32 | j. Strict-< float trigger + (d,j)
// sorted insertion reproduces the full-scan float semantics bitwise.
// Sentinel = encode(3.4e38)<<32 | 0 -> decodes to the original (3.4e38, idx 0).
#define KNN_SENTINEL 0xFF7FFFFF00000000ull
__global__ void __launch_bounds__(512) knn_kernel(const float* __restrict__ pos) {
    extern __shared__ float sm[];
    float4* sp = (float4*)sm;
    float*  cd = sm + 32768;
    int*    ci = (int*)(cd + 8192);
    const int b   = blockIdx.x >> 6;
    const int blk = blockIdx.x & 63;
    const int tid = threadIdx.x;
    const float* pb = pos + (size_t)b*NN*3;
    for (int j = tid; j < NN; j += 512) {
        float px = pb[j*3+0], py = pb[j*3+1], pz = pb[j*3+2];
        sp[j] = make_float4(px, py, pz, px*px + py*py + pz*pz);
    }
    __syncthreads();
    const int ql  = tid & 127;
    const int seg = tid >> 7;
    const int q   = blk*128 + ql;
    const float4 qp = sp[q];
    const int j0 = seg*2048, j1 = j0 + 2048;

    unsigned long long bk[KK];
    #pragma unroll
    for (int t = 0; t < KK; t++) bk[t] = KNN_SENTINEL;
    float thr = 3.4e38f;

    #pragma unroll 2
    for (int j = j0; j < j1; j++) {
        float4 c = sp[j];
        float d = qp.w + c.w - 2.f*(qp.x*c.x + qp.y*c.y + qp.z*c.z);
        if (d < thr) {
            uint32_t db = __float_as_uint(d);
            uint32_t s  = db ^ ((uint32_t)(((int)db) >> 31) | 0x80000000u);
            unsigned long long key = ((unsigned long long)s << 32) | (unsigned)j;
            #pragma unroll
            for (int t = 0; t < KK; t++) {
                unsigned long long old = bk[t];
                unsigned long long mn = (key < old) ? key : old;
                key = (key < old) ? old : key;
                bk[t] = mn;
            }
            uint32_t s15 = (uint32_t)(bk[KK-1] >> 32);
            uint32_t b15 = (s15 & 0x80000000u) ? (s15 ^ 0x80000000u) : ~s15;
            thr = __uint_as_float(b15);
        }
    }
    {
        int row = tid*16;
        #pragma unroll
        for (int t = 0; t < KK; t++) {
            uint32_t s = (uint32_t)(bk[t] >> 32);
            uint32_t bb2 = (s & 0x80000000u) ? (s ^ 0x80000000u) : ~s;
            cd[row+t] = __uint_as_float(bb2);
            ci[row+t] = (int)(uint32_t)(bk[t] & 0xffffffffu);
        }
    }
    __syncthreads();

    // merge 4 sorted lists per query; on ties prefer lower segment (= lower j)
    if (tid < 128) {
        int p[4] = {0,0,0,0};
        int base[4];
        #pragma unroll
        for (int s = 0; s < 4; s++) base[s] = (s*128 + ql)*16;
        const int obase = (b*NN + q)*KK;
        #pragma unroll
        for (int t = 0; t < KK; t++) {
            float best = 3.5e38f; int bs = 0;
            #pragma unroll
            for (int s = 0; s < 4; s++) {
                float v = (p[s] < 16) ? cd[base[s] + p[s]] : 3.6e38f;
                if (v < best) { best = v; bs = s; }
            }
            d_nbr[obase + t] = b*NN + ci[base[bs] + p[bs]];
            p[bs]++;
        }
    }
}

// ---------------- fused u + self kernel (all-MMA) ----------------
#define US_W1H 0
#define US_W1L 34816
#define US_W2H 69632
#define US_W2L 104448
#define US_AH  139264
#define US_AL  174080
#define US_POS 208896
#define US_WP  210432
#define US_B1  211968
#define US_B2  212480
#define US_SMEM 212992

__global__ void __launch_bounds__(512) u_self_kernel(const float* __restrict__ x,
                                                     const float* __restrict__ pos,
                                                     const float* __restrict__ b1,
                                                     const float* __restrict__ b2) {
    extern __shared__ char smem[];
    __nv_bfloat16* W1H = (__nv_bfloat16*)(smem + US_W1H);
    __nv_bfloat16* W1L = (__nv_bfloat16*)(smem + US_W1L);
    __nv_bfloat16* W2H = (__nv_bfloat16*)(smem + US_W2H);
    __nv_bfloat16* W2L = (__nv_bfloat16*)(smem + US_W2L);
    __nv_bfloat16* AH  = (__nv_bfloat16*)(smem + US_AH);
    __nv_bfloat16* AL  = (__nv_bfloat16*)(smem + US_AL);
    float* posS = (float*)(smem + US_POS);
    float* wpS  = (float*)(smem + US_WP);
    float* b1s  = (float*)(smem + US_B1);
    float* b2s  = (float*)(smem + US_B2);

    const int tid  = threadIdx.x;
    const int wid  = tid >> 5;
    const int lane = tid & 31;
    const int g0   = blockIdx.x * 128;

    {
        uint4* s1 = (uint4*)W1H; const uint4* g1 = (const uint4*)d_w1h;
        uint4* s2 = (uint4*)W1L; const uint4* g2 = (const uint4*)d_w1l;
        uint4* s3 = (uint4*)W2H; const uint4* g3 = (const uint4*)d_w2h;
        uint4* s4 = (uint4*)W2L; const uint4* g4 = (const uint4*)d_w2l;
        for (int i = tid; i < 2176; i += 512) {
            s1[i] = g1[i]; s2[i] = g2[i]; s3[i] = g3[i]; s4[i] = g4[i];
        }
    }
    if (tid < 384) {
        posS[tid] = pos[(size_t)g0*3 + tid];
        int o = tid/3, j = tid - o*3;
        wpS[tid] = d_w1p[o*3 + j];
    }
    if (tid < 128) { b1s[tid] = b1[tid]; b2s[tid] = b2[tid]; }
    {
        const int c0 = lane*4;
        for (int r = wid; r < 128; r += 16) {
            float4 v = *(const float4*)&x[(size_t)(g0+r)*128 + c0];
            split_store(AH, AL, r*WS2 + c0,     v.x, v.y);
            split_store(AH, AL, r*WS2 + c0 + 2, v.z, v.w);
        }
    }
    __syncthreads();

    const int wm = wid >> 2, wn = wid & 3;
    const int m0 = wm*32, n0 = wn*32;
    const int rA = lane >> 2;
    const uint32_t aoff = AOFF(lane), boff = BOFF(lane);
    const uint32_t AHu = smem_u32(AH), ALu = smem_u32(AL);
    const uint32_t W1Hu = smem_u32(W1H), W1Lu = smem_u32(W1L);
    const uint32_t W2Hu = smem_u32(W2H), W2Lu = smem_u32(W2L);
    float acc[2][4][4];
    #pragma unroll
    for (int mt = 0; mt < 2; mt++)
        #pragma unroll
        for (int nt = 0; nt < 4; nt++)
            #pragma unroll
            for (int q = 0; q < 4; q++) acc[mt][nt][q] = 0.f;

    GEMM_TERM44(AHu, W1Hu, acc)
    GEMM_TERM44(AHu, W1Lu, acc)
    GEMM_TERM44(ALu, W1Hu, acc)

    __nv_bfloat162 hhi[2][4][2], hlo[2][4][2];
    #pragma unroll
    for (int mt = 0; mt < 2; mt++) {
        const int row0 = m0 + mt*16 + rA, row1 = row0 + 8;
        float p00 = posS[row0*3], p01 = posS[row0*3+1], p02 = posS[row0*3+2];
        float p10 = posS[row1*3], p11 = posS[row1*3+1], p12 = posS[row1*3+2];
        #pragma unroll
        for (int nt = 0; nt < 4; nt++) {
            const int col0 = n0 + nt*8 + (lane & 3)*2;
            float wa0 = wpS[col0*3], wa1 = wpS[col0*3+1], wa2 = wpS[col0*3+2];
            float wb0 = wpS[col0*3+3], wb1 = wpS[col0*3+4], wb2 = wpS[col0*3+5];
            float u00 = fmaf(p02, wa2, fmaf(p01, wa1, fmaf(p00, wa0, acc[mt][nt][0])));
            float u01 = fmaf(p02, wb2, fmaf(p01, wb1, fmaf(p00, wb0, acc[mt][nt][1])));
            float u10 = fmaf(p12, wa2, fmaf(p11, wa1, fmaf(p10, wa0, acc[mt][nt][2])));
            float u11 = fmaf(p12, wb2, fmaf(p11, wb1, fmaf(p10, wb0, acc[mt][nt][3])));
            *(float2*)&d_u[(size_t)(g0+row0)*128 + col0] = make_float2(u00, u01);
            *(float2*)&d_u[(size_t)(g0+row1)*128 + col0] = make_float2(u10, u11);
            float h00 = fmaxf(acc[mt][nt][0] + b1s[col0],   0.f);
            float h01 = fmaxf(acc[mt][nt][1] + b1s[col0+1], 0.f);
            float h10 = fmaxf(acc[mt][nt][2] + b1s[col0],   0.f);
            float h11 = fmaxf(acc[mt][nt][3] + b1s[col0+1], 0.f);
            __nv_bfloat162 hi0 = __floats2bfloat162_rn(h00, h01);
            __nv_bfloat162 hi1 = __floats2bfloat162_rn(h10, h11);
            hhi[mt][nt][0] = hi0;
            hhi[mt][nt][1] = hi1;
            hlo[mt][nt][0] = __floats2bfloat162_rn(h00 - __low2float(hi0), h01 - __high2float(hi0));
            hlo[mt][nt][1] = __floats2bfloat162_rn(h10 - __low2float(hi1), h11 - __high2float(hi1));
        }
    }
    __syncthreads();
    #pragma unroll
    for (int mt = 0; mt < 2; mt++) {
        const int row0 = m0 + mt*16 + rA, row1 = row0 + 8;
        #pragma unroll
        for (int nt = 0; nt < 4; nt++) {
            const int col0 = n0 + nt*8 + (lane & 3)*2;
            *(__nv_bfloat162*)&AH[row0*WS2 + col0] = hhi[mt][nt][0];
            *(__nv_bfloat162*)&AH[row1*WS2 + col0] = hhi[mt][nt][1];
            *(__nv_bfloat162*)&AL[row0*WS2 + col0] = hlo[mt][nt][0];
            *(__nv_bfloat162*)&AL[row1*WS2 + col0] = hlo[mt][nt][1];
        }
    }
    __syncthreads();

    #pragma unroll
    for (int mt = 0; mt < 2; mt++)
        #pragma unroll
        for (int nt = 0; nt < 4; nt++)
            #pragma unroll
            for (int q = 0; q < 4; q++) acc[mt][nt][q] = 0.f;
    GEMM_TERM44(AHu, W2Hu, acc)
    GEMM_TERM44(AHu, W2Lu, acc)
    GEMM_TERM44(ALu, W2Hu, acc)

    #pragma unroll
    for (int mt = 0; mt < 2; mt++) {
        const int row0 = m0 + mt*16 + rA, row1 = row0 + 8;
        #pragma unroll
        for (int nt = 0; nt < 4; nt++) {
            const int col0 = n0 + nt*8 + (lane & 3)*2;
            float s00 = 1.f/(1.f + __expf(-(acc[mt][nt][0] + b2s[col0])));
            float s01 = 1.f/(1.f + __expf(-(acc[mt][nt][1] + b2s[col0+1])));
            float s10 = 1.f/(1.f + __expf(-(acc[mt][nt][2] + b2s[col0])));
            float s11 = 1.f/(1.f + __expf(-(acc[mt][nt][3] + b2s[col0+1])));
            *(float2*)&d_wself[(size_t)(g0+row0)*128 + col0] = make_float2(s00, s01);
            *(float2*)&d_wself[(size_t)(g0+row1)*128 + col0] = make_float2(s10, s11);
        }
    }
}

// ---------------- fused neighbor kernel: mma.sync bf16-split, 2 CTAs/SM ----------------
// Term order: AhBh, AlBh (AL built alongside AH, one gather), then WL loaded
// into the AL slot (coalesced) for AhBl. No hid rebuild.
#define NB_WH   0
#define NB_AH   34816
#define NB_S2   69632
#define NB_XG   34816
#define NB_XNS  104448
#define NB_UCEN 108544
#define NB_B1   112640
#define NB_B2   113152
#define NB_NIDX 113664
#define NB_SMEM 114176

__global__ void __launch_bounds__(256, 2) neighbor_kernel(const float* __restrict__ x,
                                const float* __restrict__ b1, const float* __restrict__ b2) {
    extern __shared__ char smem[];
    __nv_bfloat16* WH = (__nv_bfloat16*)(smem + NB_WH);
    __nv_bfloat16* AH = (__nv_bfloat16*)(smem + NB_AH);
    __nv_bfloat16* S2 = (__nv_bfloat16*)(smem + NB_S2);
    float* xg   = (float*)(smem + NB_XG);
    float* xns  = (float*)(smem + NB_XNS);
    float* ucen = (float*)(smem + NB_UCEN);
    float* b1s  = (float*)(smem + NB_B1);
    float* b2s  = (float*)(smem + NB_B2);
    int*   nidx = (int*)  (smem + NB_NIDX);

    const int tid  = threadIdx.x;
    const int wid  = tid >> 5;
    const int lane = tid & 31;
    const int g0   = blockIdx.x * 8;

    {
        const uint4* whg = (const uint4*)d_w2h;
        uint4* whs = (uint4*)WH;
        for (int i = tid; i < 2176; i += 256) whs[i] = whg[i];
    }
    if (tid < 128) { nidx[tid] = d_nbr[g0*KK + tid]; b1s[tid] = b1[tid]; b2s[tid] = b2[tid]; }
    for (int i = tid; i < 1024; i += 256) {
        int p = i >> 7, c = i & 127;
        ucen[i] = d_u[(size_t)(g0+p)*128 + c];
        xns[i]  = x  [(size_t)(g0+p)*128 + c];
    }
    __syncthreads();

    // build hidden hi (AH) AND lo (S2) in ONE pass
    const int c0 = lane*4;
    for (int r = wid; r < 128; r += 8) {
        int p = r >> 4;
        float4 uv = *reinterpret_cast<const float4*>(&d_u[(size_t)nidx[r]*128 + c0]);
        float h0 = fmaxf(uv.x - ucen[p*128 + c0+0] + b1s[c0+0], 0.f);
        float h1 = fmaxf(uv.y - ucen[p*128 + c0+1] + b1s[c0+1], 0.f);
        float h2 = fmaxf(uv.z - ucen[p*128 + c0+2] + b1s[c0+2], 0.f);
        float h3 = fmaxf(uv.w - ucen[p*128 + c0+3] + b1s[c0+3], 0.f);
        __nv_bfloat162 hA = __floats2bfloat162_rn(h0, h1);
        __nv_bfloat162 hB = __floats2bfloat162_rn(h2, h3);
        __nv_bfloat162 lA = __floats2bfloat162_rn(h0 - __low2float(hA), h1 - __high2float(hA));
        __nv_bfloat162 lB = __floats2bfloat162_rn(h2 - __low2float(hB), h3 - __high2float(hB));
        *(__nv_bfloat162*)&AH[r*WS2 + c0]     = hA;
        *(__nv_bfloat162*)&AH[r*WS2 + c0 + 2] = hB;
        *(__nv_bfloat162*)&S2[r*WS2 + c0]     = lA;
        *(__nv_bfloat162*)&S2[r*WS2 + c0 + 2] = lB;
    }
    __syncthreads();

    const int wm = wid >> 1, wn = wid & 1;
    const int m0 = wm*32, n0 = wn*64;
    const int rA = lane >> 2;
    const uint32_t aoff = AOFF(lane), boff = BOFF(lane);
    const uint32_t WHu = smem_u32(WH), AHu = smem_u32(AH), S2u = smem_u32(S2);
    float acc[2][8][4];
    #pragma unroll
    for (int mt = 0; mt < 2; mt++)
        #pragma unroll
        for (int nt = 0; nt < 8; nt++)
            #pragma unroll
            for (int q = 0; q < 4; q++) acc[mt][nt][q] = 0.f;

    GEMM_TERM48(AHu, WHu)    // Ah * Bh
    GEMM_TERM48(S2u, WHu)    // Al * Bh
    __syncthreads();

    // overwrite S2 with WL (coalesced global load)
    {
        const uint4* wlg = (const uint4*)d_w2l;
        uint4* wls = (uint4*)S2;
        for (int i = tid; i < 2176; i += 256) wls[i] = wlg[i];
    }
    __syncthreads();

    GEMM_TERM48(AHu, S2u)    // Ah * Bl
    __syncthreads();

    for (int r = wid; r < 128; r += 8)
        *reinterpret_cast<float4*>(&xg[r*132 + c0]) =
            *reinterpret_cast<const float4*>(&x[(size_t)nidx[r]*128 + c0]);
    __syncthreads();

    #pragma unroll
    for (int mt = 0; mt < 2; mt++) {
        const int p  = wm*2 + mt;
        const int r0 = m0 + mt*16 + rA;
        const int r1 = r0 + 8;
        #pragma unroll
        for (int nt = 0; nt < 8; nt++) {
            const int col0 = n0 + nt*8 + (lane & 3)*2;
            float z00 = acc[mt][nt][0] + b2s[col0];
            float z01 = acc[mt][nt][1] + b2s[col0+1];
            float z10 = acc[mt][nt][2] + b2s[col0];
            float z11 = acc[mt][nt][3] + b2s[col0+1];
            float s00 = 1.f/(1.f + __expf(-z00));
            float s01 = 1.f/(1.f + __expf(-z01));
            float s10 = 1.f/(1.f + __expf(-z10));
            float s11 = 1.f/(1.f + __expf(-z11));
            float xc0 = xns[p*128 + col0], xc1 = xns[p*128 + col0+1];
            float t0 = (xg[r0*132 + col0]   - xc0)*s00 + (xg[r1*132 + col0]   - xc0)*s10;
            float t1 = (xg[r0*132 + col0+1] - xc1)*s01 + (xg[r1*132 + col0+1] - xc1)*s11;
            t0 += __shfl_xor_sync(0xffffffffu, t0, 4);
            t0 += __shfl_xor_sync(0xffffffffu, t0, 8);
            t0 += __shfl_xor_sync(0xffffffffu, t0, 16);
            t1 += __shfl_xor_sync(0xffffffffu, t1, 4);
            t1 += __shfl_xor_sync(0xffffffffu, t1, 8);
            t1 += __shfl_xor_sync(0xffffffffu, t1, 16);
            if (lane < 4) {
                const size_t ob = (size_t)(g0+p)*128;
                float w0 = d_wself[ob + col0], w1 = d_wself[ob + col0+1];
                d_res[ob + col0]   = xc0*(1.f + w0) - t0;
                d_res[ob + col0+1] = xc1*(1.f + w1) - t1;
            }
        }
    }
}

// ---------------- unified MMA tail GEMM ----------------
#define T_WH  0
#define T_WL  34816
#define T_AH  69632
#define T_AL  104448
#define T_BS  139264
#define T_SMEM 139776

__global__ void __launch_bounds__(512) tail_kernel(int mode, const float* __restrict__ bias,
                                                   float* __restrict__ out) {
    extern __shared__ char smem[];
    __nv_bfloat16* WH = (__nv_bfloat16*)(smem + T_WH);
    __nv_bfloat16* WL = (__nv_bfloat16*)(smem + T_WL);
    __nv_bfloat16* AH = (__nv_bfloat16*)(smem + T_AH);
    __nv_bfloat16* AL = (__nv_bfloat16*)(smem + T_AL);
    float* bs = (float*)(smem + T_BS);

    const int tid  = threadIdx.x;
    const int wid  = tid >> 5;
    const int lane = tid & 31;
    const int g0   = blockIdx.x * 128;

    {
        const uint4* whg = (const uint4*)(mode == 1 ? d_m1h : d_m2h);
        const uint4* wlg = (const uint4*)(mode == 1 ? d_m1l : d_m2l);
        uint4* whs = (uint4*)WH;
        uint4* wls = (uint4*)WL;
        for (int i = tid; i < 2176; i += 512) { whs[i] = whg[i]; wls[i] = wlg[i]; }
    }
    if (tid < 128) bs[tid] = bias[tid];
    {
        const int c0 = lane*4;
        for (int r = wid; r < 128; r += 16) {
            float4 v;
            if (mode == 1) {
                v = *(const float4*)&d_res[(size_t)(g0+r)*128 + c0];
            } else {
                float4 t = *(const float4*)&d_t[(size_t)(g0+r)*128 + c0];
                v.x = fmaxf(fmaf(t.x, d_scale1[c0+0], d_shift1[c0+0]), 0.f);
                v.y = fmaxf(fmaf(t.y, d_scale1[c0+1], d_shift1[c0+1]), 0.f);
                v.z = fmaxf(fmaf(t.z, d_scale1[c0+2], d_shift1[c0+2]), 0.f);
                v.w = fmaxf(fmaf(t.w, d_scale1[c0+3], d_shift1[c0+3]), 0.f);
            }
            split_store(AH, AL, r*WS2 + c0,     v.x, v.y);
            split_store(AH, AL, r*WS2 + c0 + 2, v.z, v.w);
        }
    }
    __syncthreads();

    const int wm = wid >> 2, wn = wid & 3;
    const int m0 = wm*32, n0 = wn*32;
    const int rA = lane >> 2;
    const uint32_t aoff = AOFF(lane), boff = BOFF(lane);
    const uint32_t WHu = smem_u32(WH), WLu = smem_u32(WL);
    const uint32_t AHu = smem_u32(AH), ALu = smem_u32(AL);
    float acc[2][4][4];
    #pragma unroll
    for (int mt = 0; mt < 2; mt++)
        #pragma unroll
        for (int nt = 0; nt < 4; nt++)
            #pragma unroll
            for (int q = 0; q < 4; q++) acc[mt][nt][q] = 0.f;

    GEMM_TERM44(AHu, WHu, acc)
    GEMM_TERM44(AHu, WLu, acc)
    GEMM_TERM44(ALu, WHu, acc)

    float* dst = (mode == 1) ? d_t : out;
    float s[4][2], sq[4][2];
    #pragma unroll
    for (int nt = 0; nt < 4; nt++) { s[nt][0]=s[nt][1]=sq[nt][0]=sq[nt][1]=0.f; }

    #pragma unroll
    for (int mt = 0; mt < 2; mt++) {
        const int row0 = m0 + mt*16 + rA, row1 = row0 + 8;
        #pragma unroll
        for (int nt = 0; nt < 4; nt++) {
            const int col0 = n0 + nt*8 + (lane & 3)*2;
            float v00 = acc[mt][nt][0] + bs[col0];
            float v01 = acc[mt][nt][1] + bs[col0+1];
            float v10 = acc[mt][nt][2] + bs[col0];
            float v11 = acc[mt][nt][3] + bs[col0+1];
            *(float2*)&dst[(size_t)(g0+row0)*128 + col0] = make_float2(v00, v01);
            *(float2*)&dst[(size_t)(g0+row1)*128 + col0] = make_float2(v10, v11);
            s[nt][0]  += v00 + v10;      s[nt][1]  += v01 + v11;
            sq[nt][0] += v00*v00 + v10*v10;
            sq[nt][1] += v01*v01 + v11*v11;
        }
    }
    #pragma unroll
    for (int nt = 0; nt < 4; nt++) {
        #pragma unroll
        for (int j = 0; j < 2; j++) {
            s[nt][j]  += __shfl_xor_sync(0xffffffffu, s[nt][j], 4);
            s[nt][j]  += __shfl_xor_sync(0xffffffffu, s[nt][j], 8);
            s[nt][j]  += __shfl_xor_sync(0xffffffffu, s[nt][j], 16);
            sq[nt][j] += __shfl_xor_sync(0xffffffffu, sq[nt][j], 4);
            sq[nt][j] += __shfl_xor_sync(0xffffffffu, sq[nt][j], 8);
            sq[nt][j] += __shfl_xor_sync(0xffffffffu, sq[nt][j], 16);
        }
    }
    __syncthreads();
    float* ps  = (float*)WH;
    float* ps2 = ps + 512;
    if (lane < 4) {
        #pragma unroll
        for (int nt = 0; nt < 4; nt++) {
            const int col0 = n0 + nt*8 + lane*2;
            ps [wm*128 + col0]   = s[nt][0];
            ps [wm*128 + col0+1] = s[nt][1];
            ps2[wm*128 + col0]   = sq[nt][0];
            ps2[wm*128 + col0+1] = sq[nt][1];
        }
    }
    __syncthreads();
    if (tid < 128) {
        float a = 0.f, b = 0.f;
        #pragma unroll
        for (int g = 0; g < 4; g++) { a += ps[g*128 + tid]; b += ps2[g*128 + tid]; }
        d_p1[blockIdx.x*128 + tid] = a;
        d_p2[blockIdx.x*128 + tid] = b;
    }
}

// ---------------- BN finalize / apply ----------------
__global__ void bn_finalize_kernel(const float* __restrict__ g, const float* __restrict__ be,
                                   int which) {
    const int o = threadIdx.x;
    float s = 0.f, s2 = 0.f;
    for (int b = 0; b < 128; b++) { s += d_p1[b*128 + o]; s2 += d_p2[b*128 + o]; }
    float mu  = s  * (1.f/16384.f);
    float var = s2 * (1.f/16384.f) - mu*mu;
    float sc  = g[o] * rsqrtf(var + EPS);
    if (which == 0) { d_scale1[o] = sc; d_shift1[o] = be[o] - mu*sc; }
    else            { d_scale2[o] = sc; d_shift2[o] = be[o] - mu*sc; }
}

__global__ void bn_apply_kernel(float* __restrict__ out) {
    int i = blockIdx.x*blockDim.x + threadIdx.x;
    int o = i & 127;
    out[i] = fmaf(out[i], d_scale2[o], d_shift2[o]);
}

// ---------------- launch ----------------
extern "C" void kernel_launch(void* const* d_in, const int* in_sizes, int n_in,
                              void* d_out, int out_size) {
    (void)in_sizes; (void)n_in; (void)out_size;
    const float* x   = (const float*)d_in[0];
    const float* pos = (const float*)d_in[1];
    const float* w1  = (const float*)d_in[2];
    const float* b1  = (const float*)d_in[3];
    const float* w2  = (const float*)d_in[4];
    const float* b2  = (const float*)d_in[5];
    const float* m1  = (const float*)d_in[6];
    const float* mb1 = (const float*)d_in[7];
    const float* m2  = (const float*)d_in[8];
    const float* mb2 = (const float*)d_in[9];
    const float* g1  = (const float*)d_in[10];
    const float* be1 = (const float*)d_in[11];
    const float* g2  = (const float*)d_in[12];
    const float* be2 = (const float*)d_in[13];
    float* out = (float*)d_out;

    const int SMEM_KNN = (32768 + 8192 + 8192) * 4;   // 196608

    cudaFuncSetAttribute(knn_kernel,      cudaFuncAttributeMaxDynamicSharedMemorySize, SMEM_KNN);
    cudaFuncSetAttribute(u_self_kernel,   cudaFuncAttributeMaxDynamicSharedMemorySize, US_SMEM);
    cudaFuncSetAttribute(neighbor_kernel, cudaFuncAttributeMaxDynamicSharedMemorySize, NB_SMEM);
    cudaFuncSetAttribute(tail_kernel,     cudaFuncAttributeMaxDynamicSharedMemorySize, T_SMEM);

    prep_kernel<<<64, 256>>>(w1, w2, m1, m2);
    knn_kernel<<<128, 512, SMEM_KNN>>>(pos);
    u_self_kernel<<<NPTS/128, 512, US_SMEM>>>(x, pos, b1, b2);
    neighbor_kernel<<<NPTS/8, 256, NB_SMEM>>>(x, b1, b2);
    tail_kernel<<<NPTS/128, 512, T_SMEM>>>(1, mb1, out);
    bn_finalize_kernel<<<1, 128>>>(g1, be1, 0);
    tail_kernel<<<NPTS/128, 512, T_SMEM>>>(2, mb2, out);
    bn_finalize_kernel<<<1, 128>>>(g2, be2, 1);
    bn_apply_kernel<<<(NPTS*CC)/256, 256>>>(out);
}

// round 15
// speedup vs baseline: 1.6231x; 1.6231x over previous
#include <cuda_runtime.h>
#include <cuda_bf16.h>
#include <cstdint>

// Problem constants
#define BB 2
#define NN 8192
#define CC 128
#define PP 3
#define KK 16
#define NPTS (BB*NN)          // 16384 total points
#define EPS 1e-5f

#define WS2 136               // bf16 row stride for MMA operands (conflict-free)

// ---------------- scratch (static device globals; no allocation) ----------------
__device__ __nv_bfloat16 d_w1h[128*WS2];  // W1x hi-split [o][c]
__device__ __nv_bfloat16 d_w1l[128*WS2];
__device__ float         d_w1p[128*3];    // W1 pos part (exact fp32)
__device__ __nv_bfloat16 d_w2h[128*WS2];
__device__ __nv_bfloat16 d_w2l[128*WS2];
__device__ __nv_bfloat16 d_m1h[128*WS2];
__device__ __nv_bfloat16 d_m1l[128*WS2];
__device__ __nv_bfloat16 d_m2h[128*WS2];
__device__ __nv_bfloat16 d_m2l[128*WS2];
__device__ int   d_nbr[NPTS*KK];
__device__ float d_u [NPTS*CC];
__device__ float d_wself[NPTS*CC];
__device__ float d_res[NPTS*CC];
__device__ float d_t [NPTS*CC];
__device__ float d_p1[128*128];
__device__ float d_p2[128*128];
__device__ float d_scale1[CC], d_shift1[CC], d_scale2[CC], d_shift2[CC];

// ---------------- mma/ldmatrix helpers (baseline PTX) ----------------
__device__ __forceinline__ void mma16816(float* c, const uint32_t* a, const uint32_t* b) {
    asm volatile(
        "mma.sync.aligned.m16n8k16.row.col.f32.bf16.bf16.f32 "
        "{%0,%1,%2,%3}, {%4,%5,%6,%7}, {%8,%9}, {%0,%1,%2,%3};"
        : "+f"(c[0]), "+f"(c[1]), "+f"(c[2]), "+f"(c[3])
        : "r"(a[0]), "r"(a[1]), "r"(a[2]), "r"(a[3]), "r"(b[0]), "r"(b[1]));
}
__device__ __forceinline__ void ldsm_x4(uint32_t addr, uint32_t* r) {
    asm volatile("ldmatrix.sync.aligned.m8n8.x4.shared.b16 {%0,%1,%2,%3}, [%4];"
        : "=r"(r[0]), "=r"(r[1]), "=r"(r[2]), "=r"(r[3]) : "r"(addr));
}
__device__ __forceinline__ uint32_t smem_u32(const void* p) {
    return (uint32_t)__cvta_generic_to_shared(p);
}
__device__ __forceinline__ void split_store(__nv_bfloat16* H, __nv_bfloat16* L,
                                            int off, float a, float b) {
    __nv_bfloat162 hi = __floats2bfloat162_rn(a, b);
    __nv_bfloat162 lo = __floats2bfloat162_rn(a - __low2float(hi), b - __high2float(hi));
    *(__nv_bfloat162*)&H[off] = hi;
    *(__nv_bfloat162*)&L[off] = lo;
}

// ldmatrix lane offsets (bytes) — reproduce the scalar fragment layout exactly.
#define AOFF(lane) ((uint32_t)((((lane)&7) + (((lane)>>3)&1)*8)*WS2*2 + ((lane)>>4)*16))
#define BOFF(lane) ((uint32_t)((((lane)&7) + ((lane)>>4)*8)*WS2*2 + (((lane)>>3)&1)*16))

// GEMM term, 32x32 warp tile (4 nt), acc[2][4][4]
#define GEMM_TERM44(Au, Bu, ACC_) \
    { \
        const uint32_t ab = (Au) + (uint32_t)(m0*WS2*2) + aoff; \
        const uint32_t bb = (Bu) + (uint32_t)(n0*WS2*2) + boff; \
        _Pragma("unroll") \
        for (int kk = 0; kk < 128; kk += 16) { \
            uint32_t a[2][4], bfr[2][4]; \
            ldsm_x4(ab + (kk<<1), a[0]); \
            ldsm_x4(ab + 16*WS2*2 + (kk<<1), a[1]); \
            _Pragma("unroll") \
            for (int j = 0; j < 2; j++) ldsm_x4(bb + j*16*WS2*2 + (kk<<1), bfr[j]); \
            _Pragma("unroll") \
            for (int mt = 0; mt < 2; mt++) \
                _Pragma("unroll") \
                for (int j = 0; j < 2; j++) { \
                    mma16816(ACC_[mt][2*j],   a[mt], &bfr[j][0]); \
                    mma16816(ACC_[mt][2*j+1], a[mt], &bfr[j][2]); \
                } \
        } \
    }

// GEMM term, 32x64 warp tile (8 nt), acc[2][8][4]
#define GEMM_TERM48(Au, Bu) \
    { \
        const uint32_t ab = (Au) + (uint32_t)(m0*WS2*2) + aoff; \
        const uint32_t bb = (Bu) + (uint32_t)(n0*WS2*2) + boff; \
        _Pragma("unroll") \
        for (int kk = 0; kk < 128; kk += 16) { \
            uint32_t a[2][4], bfr[4][4]; \
            ldsm_x4(ab + (kk<<1), a[0]); \
            ldsm_x4(ab + 16*WS2*2 + (kk<<1), a[1]); \
            _Pragma("unroll") \
            for (int j = 0; j < 4; j++) ldsm_x4(bb + j*16*WS2*2 + (kk<<1), bfr[j]); \
            _Pragma("unroll") \
            for (int mt = 0; mt < 2; mt++) \
                _Pragma("unroll") \
                for (int j = 0; j < 4; j++) { \
                    mma16816(acc[mt][2*j],   a[mt], &bfr[j][0]); \
                    mma16816(acc[mt][2*j+1], a[mt], &bfr[j][2]); \
                } \
        } \
    }

// ---------------- prep: build all bf16 weight splits ----------------
__global__ void prep_kernel(const float* __restrict__ w1, const float* __restrict__ w2,
                            const float* __restrict__ m1, const float* __restrict__ m2) {
    int i = blockIdx.x*blockDim.x + threadIdx.x;
    if (i < 128*128) {
        int o = i>>7, c = i&127;
        int off = o*WS2 + c;
        {
            float w = w1[o*131 + c];
            __nv_bfloat16 hi = __float2bfloat16(w);
            d_w1h[off] = hi; d_w1l[off] = __float2bfloat16(w - __bfloat162float(hi));
        }
        {
            float w = w2[i];
            __nv_bfloat16 hi = __float2bfloat16(w);
            d_w2h[off] = hi; d_w2l[off] = __float2bfloat16(w - __bfloat162float(hi));
        }
        {
            float w = m1[i];
            __nv_bfloat16 hi = __float2bfloat16(w);
            d_m1h[off] = hi; d_m1l[off] = __float2bfloat16(w - __bfloat162float(hi));
        }
        {
            float w = m2[i];
            __nv_bfloat16 hi = __float2bfloat16(w);
            d_m2h[off] = hi; d_m2l[off] = __float2bfloat16(w - __bfloat162float(hi));
        }
        if (c < 3) d_w1p[o*3 + c] = w1[o*131 + 128 + c];
    }
}

// ---------------- KNN: 4 threads per query, two-pass (threshold + capture) --------
__global__ void __launch_bounds__(512) knn_kernel(const float* __restrict__ pos) {
    extern __shared__ float sm[];
    float4* sp = (float4*)sm;
    float*  cd = sm + 32768;
    int*    ci = (int*)(cd + 8192);
    const int b   = blockIdx.x >> 6;
    const int blk = blockIdx.x & 63;
    const int tid = threadIdx.x;
    const float* pb = pos + (size_t)b*NN*3;
    for (int j = tid; j < NN; j += 512) {
        float px = pb[j*3+0], py = pb[j*3+1], pz = pb[j*3+2];
        sp[j] = make_float4(px, py, pz, px*px + py*py + pz*pz);
    }
    __syncthreads();
    const int ql  = tid & 127;
    const int seg = tid >> 7;
    const int q   = blk*128 + ql;
    const float4 qp = sp[q];
    const int j0 = seg*2048, j1 = j0 + 2048;

    // ---- pass 1: values-only sorted top-16 ----
    float bd[KK];
    #pragma unroll
    for (int t = 0; t < KK; t++) bd[t] = 3.4e38f;
    #pragma unroll 2
    for (int j = j0; j < j1; j++) {
        float4 c = sp[j];
        float d = qp.w + c.w - 2.f*(qp.x*c.x + qp.y*c.y + qp.z*c.z);
        if (d < bd[KK-1]) {
            float dd = d;
            #pragma unroll
            for (int t = 0; t < KK; t++) {
                float mn = fminf(bd[t], dd);
                dd = fmaxf(bd[t], dd);
                bd[t] = mn;
            }
        }
    }
    const float tau = bd[KK-1];

    // ---- pass 2: capture all candidates with d <= tau, in scan order ----
    unsigned long long capb[24];
    int cnt = 0;
    #pragma unroll 2
    for (int j = j0; j < j1; j++) {
        float4 c = sp[j];
        float d = qp.w + c.w - 2.f*(qp.x*c.x + qp.y*c.y + qp.z*c.z);
        if (d <= tau && cnt < 24) {
            capb[cnt] = ((unsigned long long)__float_as_uint(d) << 32) | (unsigned)j;
            cnt++;
        }
    }

    // ---- replay exact strict-< insertion over captured set ----
    float bd2[KK]; int bi2[KK];
    #pragma unroll
    for (int t = 0; t < KK; t++) { bd2[t] = 3.4e38f; bi2[t] = 0; }
    for (int cix = 0; cix < cnt; cix++) {
        unsigned long long v = capb[cix];
        float dd = __uint_as_float((unsigned)(v >> 32));
        int   ii = (int)(unsigned)(v & 0xffffffffu);
        if (dd < bd2[KK-1]) {
            #pragma unroll
            for (int t = 0; t < KK; t++) {
                if (dd < bd2[t]) {
                    float tf = bd2[t]; bd2[t] = dd; dd = tf;
                    int   ti = bi2[t]; bi2[t] = ii; ii = ti;
                }
            }
        }
    }
    {
        int row = tid*16;
        #pragma unroll
        for (int t = 0; t < KK; t++) { cd[row+t] = bd2[t]; ci[row+t] = bi2[t]; }
    }
    __syncthreads();

    // merge 4 sorted lists per query; on ties prefer lower segment (= lower j)
    if (tid < 128) {
        int p[4] = {0,0,0,0};
        int base[4];
        #pragma unroll
        for (int s = 0; s < 4; s++) base[s] = (s*128 + ql)*16;
        const int obase = (b*NN + q)*KK;
        #pragma unroll
        for (int t = 0; t < KK; t++) {
            float best = 3.5e38f; int bs = 0;
            #pragma unroll
            for (int s = 0; s < 4; s++) {
                float v = (p[s] < 16) ? cd[base[s] + p[s]] : 3.6e38f;
                if (v < best) { best = v; bs = s; }
            }
            d_nbr[obase + t] = b*NN + ci[base[bs] + p[bs]];
            p[bs]++;
        }
    }
}

// ---------------- fused u + self kernel (all-MMA) ----------------
#define US_W1H 0
#define US_W1L 34816
#define US_W2H 69632
#define US_W2L 104448
#define US_AH  139264
#define US_AL  174080
#define US_POS 208896
#define US_WP  210432
#define US_B1  211968
#define US_B2  212480
#define US_SMEM 212992

__global__ void __launch_bounds__(512) u_self_kernel(const float* __restrict__ x,
                                                     const float* __restrict__ pos,
                                                     const float* __restrict__ b1,
                                                     const float* __restrict__ b2) {
    extern __shared__ char smem[];
    __nv_bfloat16* W1H = (__nv_bfloat16*)(smem + US_W1H);
    __nv_bfloat16* W1L = (__nv_bfloat16*)(smem + US_W1L);
    __nv_bfloat16* W2H = (__nv_bfloat16*)(smem + US_W2H);
    __nv_bfloat16* W2L = (__nv_bfloat16*)(smem + US_W2L);
    __nv_bfloat16* AH  = (__nv_bfloat16*)(smem + US_AH);
    __nv_bfloat16* AL  = (__nv_bfloat16*)(smem + US_AL);
    float* posS = (float*)(smem + US_POS);
    float* wpS  = (float*)(smem + US_WP);
    float* b1s  = (float*)(smem + US_B1);
    float* b2s  = (float*)(smem + US_B2);

    const int tid  = threadIdx.x;
    const int wid  = tid >> 5;
    const int lane = tid & 31;
    const int g0   = blockIdx.x * 128;

    {
        uint4* s1 = (uint4*)W1H; const uint4* g1 = (const uint4*)d_w1h;
        uint4* s2 = (uint4*)W1L; const uint4* g2 = (const uint4*)d_w1l;
        uint4* s3 = (uint4*)W2H; const uint4* g3 = (const uint4*)d_w2h;
        uint4* s4 = (uint4*)W2L; const uint4* g4 = (const uint4*)d_w2l;
        for (int i = tid; i < 2176; i += 512) {
            s1[i] = g1[i]; s2[i] = g2[i]; s3[i] = g3[i]; s4[i] = g4[i];
        }
    }
    if (tid < 384) {
        posS[tid] = pos[(size_t)g0*3 + tid];
        int o = tid/3, j = tid - o*3;
        wpS[tid] = d_w1p[o*3 + j];
    }
    if (tid < 128) { b1s[tid] = b1[tid]; b2s[tid] = b2[tid]; }
    {
        const int c0 = lane*4;
        for (int r = wid; r < 128; r += 16) {
            float4 v = *(const float4*)&x[(size_t)(g0+r)*128 + c0];
            split_store(AH, AL, r*WS2 + c0,     v.x, v.y);
            split_store(AH, AL, r*WS2 + c0 + 2, v.z, v.w);
        }
    }
    __syncthreads();

    const int wm = wid >> 2, wn = wid & 3;
    const int m0 = wm*32, n0 = wn*32;
    const int rA = lane >> 2;
    const uint32_t aoff = AOFF(lane), boff = BOFF(lane);
    const uint32_t AHu = smem_u32(AH), ALu = smem_u32(AL);
    const uint32_t W1Hu = smem_u32(W1H), W1Lu = smem_u32(W1L);
    const uint32_t W2Hu = smem_u32(W2H), W2Lu = smem_u32(W2L);
    float acc[2][4][4];
    #pragma unroll
    for (int mt = 0; mt < 2; mt++)
        #pragma unroll
        for (int nt = 0; nt < 4; nt++)
            #pragma unroll
            for (int q = 0; q < 4; q++) acc[mt][nt][q] = 0.f;

    GEMM_TERM44(AHu, W1Hu, acc)
    GEMM_TERM44(AHu, W1Lu, acc)
    GEMM_TERM44(ALu, W1Hu, acc)

    __nv_bfloat162 hhi[2][4][2], hlo[2][4][2];
    #pragma unroll
    for (int mt = 0; mt < 2; mt++) {
        const int row0 = m0 + mt*16 + rA, row1 = row0 + 8;
        float p00 = posS[row0*3], p01 = posS[row0*3+1], p02 = posS[row0*3+2];
        float p10 = posS[row1*3], p11 = posS[row1*3+1], p12 = posS[row1*3+2];
        #pragma unroll
        for (int nt = 0; nt < 4; nt++) {
            const int col0 = n0 + nt*8 + (lane & 3)*2;
            float wa0 = wpS[col0*3], wa1 = wpS[col0*3+1], wa2 = wpS[col0*3+2];
            float wb0 = wpS[col0*3+3], wb1 = wpS[col0*3+4], wb2 = wpS[col0*3+5];
            float u00 = fmaf(p02, wa2, fmaf(p01, wa1, fmaf(p00, wa0, acc[mt][nt][0])));
            float u01 = fmaf(p02, wb2, fmaf(p01, wb1, fmaf(p00, wb0, acc[mt][nt][1])));
            float u10 = fmaf(p12, wa2, fmaf(p11, wa1, fmaf(p10, wa0, acc[mt][nt][2])));
            float u11 = fmaf(p12, wb2, fmaf(p11, wb1, fmaf(p10, wb0, acc[mt][nt][3])));
            *(float2*)&d_u[(size_t)(g0+row0)*128 + col0] = make_float2(u00, u01);
            *(float2*)&d_u[(size_t)(g0+row1)*128 + col0] = make_float2(u10, u11);
            float h00 = fmaxf(acc[mt][nt][0] + b1s[col0],   0.f);
            float h01 = fmaxf(acc[mt][nt][1] + b1s[col0+1], 0.f);
            float h10 = fmaxf(acc[mt][nt][2] + b1s[col0],   0.f);
            float h11 = fmaxf(acc[mt][nt][3] + b1s[col0+1], 0.f);
            __nv_bfloat162 hi0 = __floats2bfloat162_rn(h00, h01);
            __nv_bfloat162 hi1 = __floats2bfloat162_rn(h10, h11);
            hhi[mt][nt][0] = hi0;
            hhi[mt][nt][1] = hi1;
            hlo[mt][nt][0] = __floats2bfloat162_rn(h00 - __low2float(hi0), h01 - __high2float(hi0));
            hlo[mt][nt][1] = __floats2bfloat162_rn(h10 - __low2float(hi1), h11 - __high2float(hi1));
        }
    }
    __syncthreads();
    #pragma unroll
    for (int mt = 0; mt < 2; mt++) {
        const int row0 = m0 + mt*16 + rA, row1 = row0 + 8;
        #pragma unroll
        for (int nt = 0; nt < 4; nt++) {
            const int col0 = n0 + nt*8 + (lane & 3)*2;
            *(__nv_bfloat162*)&AH[row0*WS2 + col0] = hhi[mt][nt][0];
            *(__nv_bfloat162*)&AH[row1*WS2 + col0] = hhi[mt][nt][1];
            *(__nv_bfloat162*)&AL[row0*WS2 + col0] = hlo[mt][nt][0];
            *(__nv_bfloat162*)&AL[row1*WS2 + col0] = hlo[mt][nt][1];
        }
    }
    __syncthreads();

    #pragma unroll
    for (int mt = 0; mt < 2; mt++)
        #pragma unroll
        for (int nt = 0; nt < 4; nt++)
            #pragma unroll
            for (int q = 0; q < 4; q++) acc[mt][nt][q] = 0.f;
    GEMM_TERM44(AHu, W2Hu, acc)
    GEMM_TERM44(AHu, W2Lu, acc)
    GEMM_TERM44(ALu, W2Hu, acc)

    #pragma unroll
    for (int mt = 0; mt < 2; mt++) {
        const int row0 = m0 + mt*16 + rA, row1 = row0 + 8;
        #pragma unroll
        for (int nt = 0; nt < 4; nt++) {
            const int col0 = n0 + nt*8 + (lane & 3)*2;
            float s00 = 1.f/(1.f + __expf(-(acc[mt][nt][0] + b2s[col0])));
            float s01 = 1.f/(1.f + __expf(-(acc[mt][nt][1] + b2s[col0+1])));
            float s10 = 1.f/(1.f + __expf(-(acc[mt][nt][2] + b2s[col0])));
            float s11 = 1.f/(1.f + __expf(-(acc[mt][nt][3] + b2s[col0+1])));
            *(float2*)&d_wself[(size_t)(g0+row0)*128 + col0] = make_float2(s00, s01);
            *(float2*)&d_wself[(size_t)(g0+row1)*128 + col0] = make_float2(s10, s11);
        }
    }
}

// ---------------- fused neighbor kernel: mma.sync bf16-split, 2 CTAs/SM ----------------
// R12 variant: AH built, AhBh + AhBl, then S2 (WL slot) rebuilt as AL for AlBh.
#define NB_WH   0
#define NB_AH   34816
#define NB_S2   69632
#define NB_XG   34816
#define NB_XNS  104448
#define NB_UCEN 108544
#define NB_B1   112640
#define NB_B2   113152
#define NB_NIDX 113664
#define NB_SMEM 114176

__global__ void __launch_bounds__(256, 2) neighbor_kernel(const float* __restrict__ x,
                                const float* __restrict__ b1, const float* __restrict__ b2) {
    extern __shared__ char smem[];
    __nv_bfloat16* WH = (__nv_bfloat16*)(smem + NB_WH);
    __nv_bfloat16* AH = (__nv_bfloat16*)(smem + NB_AH);
    __nv_bfloat16* S2 = (__nv_bfloat16*)(smem + NB_S2);
    float* xg   = (float*)(smem + NB_XG);
    float* xns  = (float*)(smem + NB_XNS);
    float* ucen = (float*)(smem + NB_UCEN);
    float* b1s  = (float*)(smem + NB_B1);
    float* b2s  = (float*)(smem + NB_B2);
    int*   nidx = (int*)  (smem + NB_NIDX);

    const int tid  = threadIdx.x;
    const int wid  = tid >> 5;
    const int lane = tid & 31;
    const int g0   = blockIdx.x * 8;

    {
        const uint4* whg = (const uint4*)d_w2h;
        const uint4* wlg = (const uint4*)d_w2l;
        uint4* whs = (uint4*)WH;
        uint4* wls = (uint4*)S2;
        for (int i = tid; i < 2176; i += 256) { whs[i] = whg[i]; wls[i] = wlg[i]; }
    }
    if (tid < 128) { nidx[tid] = d_nbr[g0*KK + tid]; b1s[tid] = b1[tid]; b2s[tid] = b2[tid]; }
    for (int i = tid; i < 1024; i += 256) {
        int p = i >> 7, c = i & 127;
        ucen[i] = d_u[(size_t)(g0+p)*128 + c];
        xns[i]  = x  [(size_t)(g0+p)*128 + c];
    }
    __syncthreads();

    const int c0 = lane*4;
    for (int r = wid; r < 128; r += 8) {
        int p = r >> 4;
        float4 uv = *reinterpret_cast<const float4*>(&d_u[(size_t)nidx[r]*128 + c0]);
        float h0 = fmaxf(uv.x - ucen[p*128 + c0+0] + b1s[c0+0], 0.f);
        float h1 = fmaxf(uv.y - ucen[p*128 + c0+1] + b1s[c0+1], 0.f);
        float h2 = fmaxf(uv.z - ucen[p*128 + c0+2] + b1s[c0+2], 0.f);
        float h3 = fmaxf(uv.w - ucen[p*128 + c0+3] + b1s[c0+3], 0.f);
        __nv_bfloat162 hA = __floats2bfloat162_rn(h0, h1);
        __nv_bfloat162 hB = __floats2bfloat162_rn(h2, h3);
        *(__nv_bfloat162*)&AH[r*WS2 + c0]     = hA;
        *(__nv_bfloat162*)&AH[r*WS2 + c0 + 2] = hB;
    }
    __syncthreads();

    const int wm = wid >> 1, wn = wid & 1;
    const int m0 = wm*32, n0 = wn*64;
    const int rA = lane >> 2;
    const uint32_t aoff = AOFF(lane), boff = BOFF(lane);
    const uint32_t WHu = smem_u32(WH), AHu = smem_u32(AH), S2u = smem_u32(S2);
    float acc[2][8][4];
    #pragma unroll
    for (int mt = 0; mt < 2; mt++)
        #pragma unroll
        for (int nt = 0; nt < 8; nt++)
            #pragma unroll
            for (int q = 0; q < 4; q++) acc[mt][nt][q] = 0.f;

    GEMM_TERM48(AHu, WHu)
    GEMM_TERM48(AHu, S2u)
    __syncthreads();

    // rebuild S2 as AL (same inputs, same arithmetic -> identical lo values)
    for (int r = wid; r < 128; r += 8) {
        int p = r >> 4;
        float4 uv = *reinterpret_cast<const float4*>(&d_u[(size_t)nidx[r]*128 + c0]);
        float h0 = fmaxf(uv.x - ucen[p*128 + c0+0] + b1s[c0+0], 0.f);
        float h1 = fmaxf(uv.y - ucen[p*128 + c0+1] + b1s[c0+1], 0.f);
        float h2 = fmaxf(uv.z - ucen[p*128 + c0+2] + b1s[c0+2], 0.f);
        float h3 = fmaxf(uv.w - ucen[p*128 + c0+3] + b1s[c0+3], 0.f);
        __nv_bfloat162 hA = __floats2bfloat162_rn(h0, h1);
        __nv_bfloat162 hB = __floats2bfloat162_rn(h2, h3);
        __nv_bfloat162 lA = __floats2bfloat162_rn(h0 - __low2float(hA), h1 - __high2float(hA));
        __nv_bfloat162 lB = __floats2bfloat162_rn(h2 - __low2float(hB), h3 - __high2float(hB));
        *(__nv_bfloat162*)&S2[r*WS2 + c0]     = lA;
        *(__nv_bfloat162*)&S2[r*WS2 + c0 + 2] = lB;
    }
    __syncthreads();

    GEMM_TERM48(S2u, WHu)
    __syncthreads();

    for (int r = wid; r < 128; r += 8)
        *reinterpret_cast<float4*>(&xg[r*132 + c0]) =
            *reinterpret_cast<const float4*>(&x[(size_t)nidx[r]*128 + c0]);
    __syncthreads();

    #pragma unroll
    for (int mt = 0; mt < 2; mt++) {
        const int p  = wm*2 + mt;
        const int r0 = m0 + mt*16 + rA;
        const int r1 = r0 + 8;
        #pragma unroll
        for (int nt = 0; nt < 8; nt++) {
            const int col0 = n0 + nt*8 + (lane & 3)*2;
            float z00 = acc[mt][nt][0] + b2s[col0];
            float z01 = acc[mt][nt][1] + b2s[col0+1];
            float z10 = acc[mt][nt][2] + b2s[col0];
            float z11 = acc[mt][nt][3] + b2s[col0+1];
            float s00 = 1.f/(1.f + __expf(-z00));
            float s01 = 1.f/(1.f + __expf(-z01));
            float s10 = 1.f/(1.f + __expf(-z10));
            float s11 = 1.f/(1.f + __expf(-z11));
            float xc0 = xns[p*128 + col0], xc1 = xns[p*128 + col0+1];
            float t0 = (xg[r0*132 + col0]   - xc0)*s00 + (xg[r1*132 + col0]   - xc0)*s10;
            float t1 = (xg[r0*132 + col0+1] - xc1)*s01 + (xg[r1*132 + col0+1] - xc1)*s11;
            t0 += __shfl_xor_sync(0xffffffffu, t0, 4);
            t0 += __shfl_xor_sync(0xffffffffu, t0, 8);
            t0 += __shfl_xor_sync(0xffffffffu, t0, 16);
            t1 += __shfl_xor_sync(0xffffffffu, t1, 4);
            t1 += __shfl_xor_sync(0xffffffffu, t1, 8);
            t1 += __shfl_xor_sync(0xffffffffu, t1, 16);
            if (lane < 4) {
                const size_t ob = (size_t)(g0+p)*128;
                float w0 = d_wself[ob + col0], w1 = d_wself[ob + col0+1];
                d_res[ob + col0]   = xc0*(1.f + w0) - t0;
                d_res[ob + col0+1] = xc1*(1.f + w1) - t1;
            }
        }
    }
}

// ---------------- unified MMA tail GEMM ----------------
#define T_WH  0
#define T_WL  34816
#define T_AH  69632
#define T_AL  104448
#define T_BS  139264
#define T_SMEM 139776

__global__ void __launch_bounds__(512) tail_kernel(int mode, const float* __restrict__ bias,
                                                   float* __restrict__ out) {
    extern __shared__ char smem[];
    __nv_bfloat16* WH = (__nv_bfloat16*)(smem + T_WH);
    __nv_bfloat16* WL = (__nv_bfloat16*)(smem + T_WL);
    __nv_bfloat16* AH = (__nv_bfloat16*)(smem + T_AH);
    __nv_bfloat16* AL = (__nv_bfloat16*)(smem + T_AL);
    float* bs = (float*)(smem + T_BS);

    const int tid  = threadIdx.x;
    const int wid  = tid >> 5;
    const int lane = tid & 31;
    const int g0   = blockIdx.x * 128;

    {
        const uint4* whg = (const uint4*)(mode == 1 ? d_m1h : d_m2h);
        const uint4* wlg = (const uint4*)(mode == 1 ? d_m1l : d_m2l);
        uint4* whs = (uint4*)WH;
        uint4* wls = (uint4*)WL;
        for (int i = tid; i < 2176; i += 512) { whs[i] = whg[i]; wls[i] = wlg[i]; }
    }
    if (tid < 128) bs[tid] = bias[tid];
    {
        const int c0 = lane*4;
        for (int r = wid; r < 128; r += 16) {
            float4 v;
            if (mode == 1) {
                v = *(const float4*)&d_res[(size_t)(g0+r)*128 + c0];
            } else {
                float4 t = *(const float4*)&d_t[(size_t)(g0+r)*128 + c0];
                v.x = fmaxf(fmaf(t.x, d_scale1[c0+0], d_shift1[c0+0]), 0.f);
                v.y = fmaxf(fmaf(t.y, d_scale1[c0+1], d_shift1[c0+1]), 0.f);
                v.z = fmaxf(fmaf(t.z, d_scale1[c0+2], d_shift1[c0+2]), 0.f);
                v.w = fmaxf(fmaf(t.w, d_scale1[c0+3], d_shift1[c0+3]), 0.f);
            }
            split_store(AH, AL, r*WS2 + c0,     v.x, v.y);
            split_store(AH, AL, r*WS2 + c0 + 2, v.z, v.w);
        }
    }
    __syncthreads();

    const int wm = wid >> 2, wn = wid & 3;
    const int m0 = wm*32, n0 = wn*32;
    const int rA = lane >> 2;
    const uint32_t aoff = AOFF(lane), boff = BOFF(lane);
    const uint32_t WHu = smem_u32(WH), WLu = smem_u32(WL);
    const uint32_t AHu = smem_u32(AH), ALu = smem_u32(AL);
    float acc[2][4][4];
    #pragma unroll
    for (int mt = 0; mt < 2; mt++)
        #pragma unroll
        for (int nt = 0; nt < 4; nt++)
            #pragma unroll
            for (int q = 0; q < 4; q++) acc[mt][nt][q] = 0.f;

    GEMM_TERM44(AHu, WHu, acc)
    GEMM_TERM44(AHu, WLu, acc)
    GEMM_TERM44(ALu, WHu, acc)

    float* dst = (mode == 1) ? d_t : out;
    float s[4][2], sq[4][2];
    #pragma unroll
    for (int nt = 0; nt < 4; nt++) { s[nt][0]=s[nt][1]=sq[nt][0]=sq[nt][1]=0.f; }

    #pragma unroll
    for (int mt = 0; mt < 2; mt++) {
        const int row0 = m0 + mt*16 + rA, row1 = row0 + 8;
        #pragma unroll
        for (int nt = 0; nt < 4; nt++) {
            const int col0 = n0 + nt*8 + (lane & 3)*2;
            float v00 = acc[mt][nt][0] + bs[col0];
            float v01 = acc[mt][nt][1] + bs[col0+1];
            float v10 = acc[mt][nt][2] + bs[col0];
            float v11 = acc[mt][nt][3] + bs[col0+1];
            *(float2*)&dst[(size_t)(g0+row0)*128 + col0] = make_float2(v00, v01);
            *(float2*)&dst[(size_t)(g0+row1)*128 + col0] = make_float2(v10, v11);
            s[nt][0]  += v00 + v10;      s[nt][1]  += v01 + v11;
            sq[nt][0] += v00*v00 + v10*v10;
            sq[nt][1] += v01*v01 + v11*v11;
        }
    }
    #pragma unroll
    for (int nt = 0; nt < 4; nt++) {
        #pragma unroll
        for (int j = 0; j < 2; j++) {
            s[nt][j]  += __shfl_xor_sync(0xffffffffu, s[nt][j], 4);
            s[nt][j]  += __shfl_xor_sync(0xffffffffu, s[nt][j], 8);
            s[nt][j]  += __shfl_xor_sync(0xffffffffu, s[nt][j], 16);
            sq[nt][j] += __shfl_xor_sync(0xffffffffu, sq[nt][j], 4);
            sq[nt][j] += __shfl_xor_sync(0xffffffffu, sq[nt][j], 8);
            sq[nt][j] += __shfl_xor_sync(0xffffffffu, sq[nt][j], 16);
        }
    }
    __syncthreads();
    float* ps  = (float*)WH;
    float* ps2 = ps + 512;
    if (lane < 4) {
        #pragma unroll
        for (int nt = 0; nt < 4; nt++) {
            const int col0 = n0 + nt*8 + lane*2;
            ps [wm*128 + col0]   = s[nt][0];
            ps [wm*128 + col0+1] = s[nt][1];
            ps2[wm*128 + col0]   = sq[nt][0];
            ps2[wm*128 + col0+1] = sq[nt][1];
        }
    }
    __syncthreads();
    if (tid < 128) {
        float a = 0.f, b = 0.f;
        #pragma unroll
        for (int g = 0; g < 4; g++) { a += ps[g*128 + tid]; b += ps2[g*128 + tid]; }
        d_p1[blockIdx.x*128 + tid] = a;
        d_p2[blockIdx.x*128 + tid] = b;
    }
}

// ---------------- BN finalize / apply ----------------
__global__ void bn_finalize_kernel(const float* __restrict__ g, const float* __restrict__ be,
                                   int which) {
    const int o = threadIdx.x;
    float s = 0.f, s2 = 0.f;
    for (int b = 0; b < 128; b++) { s += d_p1[b*128 + o]; s2 += d_p2[b*128 + o]; }
    float mu  = s  * (1.f/16384.f);
    float var = s2 * (1.f/16384.f) - mu*mu;
    float sc  = g[o] * rsqrtf(var + EPS);
    if (which == 0) { d_scale1[o] = sc; d_shift1[o] = be[o] - mu*sc; }
    else            { d_scale2[o] = sc; d_shift2[o] = be[o] - mu*sc; }
}

__global__ void bn_apply_kernel(float* __restrict__ out) {
    int i = blockIdx.x*blockDim.x + threadIdx.x;
    int o = i & 127;
    out[i] = fmaf(out[i], d_scale2[o], d_shift2[o]);
}

// ---------------- launch ----------------
extern "C" void kernel_launch(void* const* d_in, const int* in_sizes, int n_in,
                              void* d_out, int out_size) {
    (void)in_sizes; (void)n_in; (void)out_size;
    const float* x   = (const float*)d_in[0];
    const float* pos = (const float*)d_in[1];
    const float* w1  = (const float*)d_in[2];
    const float* b1  = (const float*)d_in[3];
    const float* w2  = (const float*)d_in[4];
    const float* b2  = (const float*)d_in[5];
    const float* m1  = (const float*)d_in[6];
    const float* mb1 = (const float*)d_in[7];
    const float* m2  = (const float*)d_in[8];
    const float* mb2 = (const float*)d_in[9];
    const float* g1  = (const float*)d_in[10];
    const float* be1 = (const float*)d_in[11];
    const float* g2  = (const float*)d_in[12];
    const float* be2 = (const float*)d_in[13];
    float* out = (float*)d_out;

    const int SMEM_KNN = (32768 + 8192 + 8192) * 4;   // 196608

    cudaFuncSetAttribute(knn_kernel,      cudaFuncAttributeMaxDynamicSharedMemorySize, SMEM_KNN);
    cudaFuncSetAttribute(u_self_kernel,   cudaFuncAttributeMaxDynamicSharedMemorySize, US_SMEM);
    cudaFuncSetAttribute(neighbor_kernel, cudaFuncAttributeMaxDynamicSharedMemorySize, NB_SMEM);
    cudaFuncSetAttribute(tail_kernel,     cudaFuncAttributeMaxDynamicSharedMemorySize, T_SMEM);

    prep_kernel<<<64, 256>>>(w1, w2, m1, m2);
    knn_kernel<<<128, 512, SMEM_KNN>>>(pos);
    u_self_kernel<<<NPTS/128, 512, US_SMEM>>>(x, pos, b1, b2);
    neighbor_kernel<<<NPTS/8, 256, NB_SMEM>>>(x, b1, b2);
    tail_kernel<<<NPTS/128, 512, T_SMEM>>>(1, mb1, out);
    bn_finalize_kernel<<<1, 128>>>(g1, be1, 0);
    tail_kernel<<<NPTS/128, 512, T_SMEM>>>(2, mb2, out);
    bn_finalize_kernel<<<1, 128>>>(g2, be2, 1);
    bn_apply_kernel<<<(NPTS*CC)/256, 256>>>(out);
}